// round 3
// baseline (speedup 1.0000x reference)
#include <cuda_runtime.h>
#include <math.h>

// ---------------- problem constants ----------------
#define BB 16
#define T0 512
#define TR 511
#define PP 1024
#define DD 2048
#define G4 8192   // 4*D
#define NL 4

// ---------------- scratch (device globals; no allocation allowed) ----------------
__device__ __align__(16) float g_xg[(size_t)BB * T0 * G4];      // 256 MB
__device__ __align__(16) float g_bufA[(size_t)BB * T0 * PP];    // 32 MB
__device__ __align__(16) float g_bufB[(size_t)BB * T0 * PP];    // 32 MB
__device__ __align__(16) float g_convA[(size_t)BB * T0 * DD];   // 64 MB (conv im2col)
__device__ __align__(16) float g_hs[(size_t)BB * T0 * PP];      // 32 MB
__device__ __align__(16) float g_c[BB * DD];
__device__ __align__(16) float g_h[BB * PP];
__device__ __align__(16) float g_s[BB * DD];
__device__ unsigned int g_bar;

// ================= tf32 helpers =================
__device__ __forceinline__ unsigned f2tf32(float x) {
    unsigned r;
    asm("cvt.rna.tf32.f32 %0, %1;" : "=r"(r) : "f"(x));
    return r;
}
__device__ __forceinline__ void split_tf32(float x, unsigned& hi, unsigned& lo) {
    hi = f2tf32(x);
    lo = f2tf32(x - __uint_as_float(hi));
}
__device__ __forceinline__ void mma_tf32(float* c, const unsigned* a, const unsigned* b) {
    asm volatile(
        "mma.sync.aligned.m16n8k8.row.col.f32.tf32.tf32.f32 "
        "{%0,%1,%2,%3},{%4,%5,%6,%7},{%8,%9},{%0,%1,%2,%3};"
        : "+f"(c[0]), "+f"(c[1]), "+f"(c[2]), "+f"(c[3])
        : "r"(a[0]), "r"(a[1]), "r"(a[2]), "r"(a[3]), "r"(b[0]), "r"(b[1]));
}

// ================= split-tf32 GEMM: C[M,N] = A[M,K]@B[K,N] + bias =================
// BM=128, BN=128, BK=16, 256 threads = 8 warps (2m x 4n), warp tile 64x32.
// Requires K%16==0, N%128==0. M guarded.
#define GBM 128
#define GBN 128
#define GBK 16
#define ASTR (GBM + 8)
#define BSTR (GBN + 8)

__global__ __launch_bounds__(256) void gemm_tf32(
    const float* __restrict__ A, const float* __restrict__ Bw,
    const float* __restrict__ bias, float* __restrict__ C,
    int M, int N, int K)
{
    __shared__ float As[GBK][ASTR];   // [k][m]
    __shared__ float Bs[GBK][BSTR];   // [k][n]

    const int bm = blockIdx.y * GBM;
    const int bn = blockIdx.x * GBN;
    const int tid = threadIdx.x;
    const int lane = tid & 31;
    const int wid = tid >> 5;
    const int wm = (wid >> 2) * 64;   // warp m-origin within tile
    const int wn = (wid & 3) * 32;    // warp n-origin within tile

    const int lg = lane >> 2;   // 0..7
    const int lk = lane & 3;    // 0..3

    float acc[4][4][4];
#pragma unroll
    for (int mt = 0; mt < 4; mt++)
#pragma unroll
        for (int nt = 0; nt < 4; nt++)
#pragma unroll
            for (int r = 0; r < 4; r++) acc[mt][nt][r] = 0.0f;

    for (int k0 = 0; k0 < K; k0 += GBK) {
        // A tile: 128 rows x 16 k (512 float4, 2 per thread), transposed into As[k][m]
#pragma unroll
        for (int it = 0; it < 2; it++) {
            int f = tid + it * 256;
            int r = f >> 2;
            int kq = (f & 3) * 4;
            float4 v = make_float4(0.f, 0.f, 0.f, 0.f);
            if (bm + r < M) v = *(const float4*)&A[(size_t)(bm + r) * K + k0 + kq];
            As[kq + 0][r] = v.x;
            As[kq + 1][r] = v.y;
            As[kq + 2][r] = v.z;
            As[kq + 3][r] = v.w;
        }
        // B tile: 16 rows x 128 n (512 float4, 2 per thread)
#pragma unroll
        for (int it = 0; it < 2; it++) {
            int f = tid + it * 256;
            int r = f >> 5;
            int nq = (f & 31) * 4;
            float4 v = *(const float4*)&Bw[(size_t)(k0 + r) * N + bn + nq];
            *(float4*)&Bs[r][nq] = v;
        }
        __syncthreads();

#pragma unroll
        for (int kk = 0; kk < GBK; kk += 8) {
            unsigned ah[4][4], al[4][4], bh[4][2], bl[4][2];
#pragma unroll
            for (int mt = 0; mt < 4; mt++) {
                int row = wm + mt * 16 + lg;
                float a0 = As[kk + lk][row];
                float a1 = As[kk + lk][row + 8];
                float a2 = As[kk + 4 + lk][row];
                float a3 = As[kk + 4 + lk][row + 8];
                split_tf32(a0, ah[mt][0], al[mt][0]);
                split_tf32(a1, ah[mt][1], al[mt][1]);
                split_tf32(a2, ah[mt][2], al[mt][2]);
                split_tf32(a3, ah[mt][3], al[mt][3]);
            }
#pragma unroll
            for (int nt = 0; nt < 4; nt++) {
                int col = wn + nt * 8 + lg;
                float b0 = Bs[kk + lk][col];
                float b1 = Bs[kk + 4 + lk][col];
                split_tf32(b0, bh[nt][0], bl[nt][0]);
                split_tf32(b1, bh[nt][1], bl[nt][1]);
            }
#pragma unroll
            for (int mt = 0; mt < 4; mt++)
#pragma unroll
                for (int nt = 0; nt < 4; nt++) {
                    mma_tf32(acc[mt][nt], ah[mt], bh[nt]);
                    mma_tf32(acc[mt][nt], ah[mt], bl[nt]);
                    mma_tf32(acc[mt][nt], al[mt], bh[nt]);
                }
        }
        __syncthreads();
    }

    // epilogue
#pragma unroll
    for (int mt = 0; mt < 4; mt++) {
#pragma unroll
        for (int nt = 0; nt < 4; nt++) {
            int row0 = bm + wm + mt * 16 + lg;
            int col0 = bn + wn + nt * 8 + lk * 2;
            float b0 = bias[col0], b1 = bias[col0 + 1];
            if (row0 < M) {
                float2 v = make_float2(acc[mt][nt][0] + b0, acc[mt][nt][1] + b1);
                *(float2*)&C[(size_t)row0 * N + col0] = v;
            }
            if (row0 + 8 < M) {
                float2 v = make_float2(acc[mt][nt][2] + b0, acc[mt][nt][3] + b1);
                *(float2*)&C[(size_t)(row0 + 8) * N + col0] = v;
            }
        }
    }
}

// ================= persistent LSTM layer kernel =================
// grid = 128 blocks x 512 threads. Co-resident (1 block/SM). Software grid barrier.
// Phase A: gates = xg[t] + h @ Wh ; cell update -> c, s   (block owns 16 d-values x 4 gates)
// Phase B: h = s @ proj                                   (block owns 8 p-columns)
#define NBLK 128

__device__ __forceinline__ void grid_barrier(unsigned target) {
    __syncthreads();
    __threadfence();
    if (threadIdx.x == 0) {
        atomicAdd(&g_bar, 1u);
        while (*(volatile unsigned int*)&g_bar < target) {
            __nanosleep(40);
        }
    }
    __syncthreads();
}

__global__ __launch_bounds__(512, 1) void lstm_persist(
    const float* __restrict__ xg,    // (B*T, 8192)
    const float* __restrict__ Wh,    // (1024, 8192)
    const float* __restrict__ proj,  // (2048, 1024)
    float* __restrict__ c,           // (16, 2048)
    float* __restrict__ h,           // (16, 1024)
    float* __restrict__ s,           // (16, 2048)
    float* __restrict__ hs,          // (B*T, 1024)
    int T)
{
    __shared__ float smr[8192];      // 32 KB reduction buffer (reused by both phases)

    const int tid = threadIdx.x;
    const int lane = tid & 31;
    const int warp = tid >> 5;       // 0..15
    const int bid = blockIdx.x;

    // phase A thread mapping
    const int kcA = tid >> 4;        // 0..31 (32 k per chunk)
    const int di = tid & 15;        // 0..15
    const int d0 = bid * 16;
    // phase B thread mapping
    const int kcB = tid >> 1;        // 0..255 (8 k per chunk)
    const int pi2 = tid & 1;         // 0/1 (4 cols each)
    const int p0 = bid * 8;

    unsigned epoch = 0;

    for (int t = 0; t < T; t++) {
        // ---------- Phase A: gates + cell ----------
        {
            float acc[4][16];
#pragma unroll
            for (int g = 0; g < 4; g++)
#pragma unroll
                for (int b = 0; b < BB; b++) acc[g][b] = 0.0f;

            const int kbase = kcA * 32;
            for (int kb = 0; kb < 32; kb += 4) {
                const int k = kbase + kb;
                float w[4][4];
#pragma unroll
                for (int g = 0; g < 4; g++)
#pragma unroll
                    for (int kk = 0; kk < 4; kk++)
                        w[g][kk] = Wh[(size_t)(k + kk) * G4 + g * DD + d0 + di];
#pragma unroll
                for (int b = 0; b < BB; b++) {
                    float4 hv = __ldcg((const float4*)&h[b * PP + k]);
#pragma unroll
                    for (int g = 0; g < 4; g++) {
                        acc[g][b] = fmaf(hv.x, w[g][0], acc[g][b]);
                        acc[g][b] = fmaf(hv.y, w[g][1], acc[g][b]);
                        acc[g][b] = fmaf(hv.z, w[g][2], acc[g][b]);
                        acc[g][b] = fmaf(hv.w, w[g][3], acc[g][b]);
                    }
                }
            }

            // pair-reduce the two kc's within a warp (lane ^ 16)
#pragma unroll
            for (int g = 0; g < 4; g++)
#pragma unroll
                for (int b = 0; b < BB; b++)
                    acc[g][b] += __shfl_xor_sync(0xffffffffu, acc[g][b], 16);

            // cross-warp: 16 warps -> 8 slots (write then add), then 8-way sum
            const int slot = warp & 7;
            if (lane < 16 && warp < 8) {
#pragma unroll
                for (int g = 0; g < 4; g++)
#pragma unroll
                    for (int b = 0; b < BB; b++)
                        smr[((slot * 4 + g) * 16 + b) * 16 + di] = acc[g][b];
            }
            __syncthreads();
            if (lane < 16 && warp >= 8) {
#pragma unroll
                for (int g = 0; g < 4; g++)
#pragma unroll
                    for (int b = 0; b < BB; b++)
                        smr[((slot * 4 + g) * 16 + b) * 16 + di] += acc[g][b];
            }
            __syncthreads();

            if (tid < 256) {
                const int b = tid >> 4;
                const int dd = tid & 15;
                const int d = d0 + dd;
                float gsum[4];
#pragma unroll
                for (int g = 0; g < 4; g++) {
                    float v = 0.0f;
#pragma unroll
                    for (int sl = 0; sl < 8; sl++)
                        v += smr[((sl * 4 + g) * 16 + b) * 16 + dd];
                    gsum[g] = v;
                }
                const size_t xrow = ((size_t)(b * T + t)) * G4;
                float gi = gsum[0] + xg[xrow + 0 * DD + d];
                float gj = gsum[1] + xg[xrow + 1 * DD + d];
                float gf = gsum[2] + xg[xrow + 2 * DD + d];
                float go = gsum[3] + xg[xrow + 3 * DD + d];
                float si = 1.0f / (1.0f + expf(-gi));
                float sf = 1.0f / (1.0f + expf(-(gf + 1.0f)));
                float so = 1.0f / (1.0f + expf(-go));
                float cn = sf * c[b * DD + d] + si * tanhf(gj);
                c[b * DD + d] = cn;
                s[b * DD + d] = so * tanhf(cn);
            }
        }

        epoch++;
        grid_barrier(epoch * NBLK);

        // ---------- Phase B: h = s @ proj ----------
        {
            float accp[BB][4];
#pragma unroll
            for (int b = 0; b < BB; b++)
#pragma unroll
                for (int j = 0; j < 4; j++) accp[b][j] = 0.0f;

            const int kbase = kcB * 8;
#pragma unroll
            for (int kk = 0; kk < 8; kk++) {
                const int k = kbase + kk;
                float4 wv = *(const float4*)&proj[(size_t)k * PP + p0 + pi2 * 4];
#pragma unroll
                for (int b = 0; b < BB; b++) {
                    float sv = __ldcg(&s[b * DD + k]);
                    accp[b][0] = fmaf(sv, wv.x, accp[b][0]);
                    accp[b][1] = fmaf(sv, wv.y, accp[b][1]);
                    accp[b][2] = fmaf(sv, wv.z, accp[b][2]);
                    accp[b][3] = fmaf(sv, wv.w, accp[b][3]);
                }
            }

            // reduce kc within warp (16 kc values span lane bits 1..4)
#pragma unroll
            for (int off = 2; off <= 16; off <<= 1)
#pragma unroll
                for (int b = 0; b < BB; b++)
#pragma unroll
                    for (int j = 0; j < 4; j++)
                        accp[b][j] += __shfl_xor_sync(0xffffffffu, accp[b][j], off);

            // lanes 0 (pi2=0) and 1 (pi2=1) hold warp totals
            if (lane < 2) {
#pragma unroll
                for (int b = 0; b < BB; b++)
#pragma unroll
                    for (int j = 0; j < 4; j++)
                        smr[((warp * 2 + lane) * 16 + b) * 4 + j] = accp[b][j];
            }
            __syncthreads();

            if (tid < 128) {
                const int b = tid >> 3;
                const int p = tid & 7;
                const int jj = p & 3;
                const int pp2 = p >> 2;
                float v = 0.0f;
#pragma unroll
                for (int w2 = 0; w2 < 16; w2++)
                    v += smr[((w2 * 2 + pp2) * 16 + b) * 4 + jj];
                h[b * PP + p0 + p] = v;
                hs[((size_t)(b * T + t)) * PP + p0 + p] = v;
            }
            __syncthreads();   // protect smr before next phase-A use? (phase A writes after barrier anyway)
        }

        epoch++;
        grid_barrier(epoch * NBLK);
    }
}

// ================= LayerNorm over rows of 1024 =================
__global__ __launch_bounds__(256) void ln_kernel(
    const float* __restrict__ x, const float* __restrict__ gam,
    const float* __restrict__ bet, float* __restrict__ y)
{
    __shared__ float sred[256];
    const size_t r = blockIdx.x;
    const float* xr = x + r * PP;
    const int tid = threadIdx.x;

    float v[4];
#pragma unroll
    for (int i = 0; i < 4; i++) v[i] = xr[tid + i * 256];
    float sm = v[0] + v[1] + v[2] + v[3];
    sred[tid] = sm;
    __syncthreads();
    for (int off = 128; off > 0; off >>= 1) {
        if (tid < off) sred[tid] += sred[tid + off];
        __syncthreads();
    }
    float mean = sred[0] * (1.0f / 1024.0f);
    __syncthreads();

    float q = 0.0f;
#pragma unroll
    for (int i = 0; i < 4; i++) { float d = v[i] - mean; q += d * d; }
    sred[tid] = q;
    __syncthreads();
    for (int off = 128; off > 0; off >>= 1) {
        if (tid < off) sred[tid] += sred[tid + off];
        __syncthreads();
    }
    float inv = rsqrtf(sred[0] * (1.0f / 1024.0f) + 1e-3f);

#pragma unroll
    for (int i = 0; i < 4; i++) {
        int col = tid + i * 256;
        y[r * PP + col] = (v[i] - mean) * inv * gam[col] + bet[col];
    }
}

// ================= conv im2col: Acat[b*511+t][w*1024+p] = ln[b][t+w][p] =================
__global__ __launch_bounds__(256) void build_convA(
    const float* __restrict__ ln, float* __restrict__ Acat)
{
    size_t idx = (size_t)blockIdx.x * 256 + threadIdx.x;  // over 16*511*2048
    if (idx >= (size_t)BB * TR * DD) return;
    int m = (int)(idx >> 11);
    int k = (int)(idx & 2047);
    int b = m / TR;
    int t = m - b * TR;
    int w = k >> 10;
    int p = k & 1023;
    Acat[idx] = ln[((size_t)(b * T0 + t + w)) * PP + p];
}

// ================= init / reset / tail =================
__global__ __launch_bounds__(256) void init_state(
    const float* __restrict__ state, float* __restrict__ c, float* __restrict__ h)
{
    int i = blockIdx.x * 256 + threadIdx.x;
    if (i < BB * DD) c[i] = state[i];
    if (i < BB * PP) {
        int b = i >> 10, p = i & 1023;
        h[i] = state[BB * DD + b * DD + p];
    }
}

__global__ void reset_bar() { g_bar = 0u; }

__global__ __launch_bounds__(256) void write_tail(
    const float* __restrict__ c, const float* __restrict__ h, float* __restrict__ out)
{
    const size_t base = (size_t)BB * TR * PP;
    int i = blockIdx.x * 256 + threadIdx.x;
    if (i < BB * DD) out[base + i] = c[i];
    if (i < BB * PP) out[base + BB * DD + i] = h[i];
}

// ================= orchestration =================
extern "C" void kernel_launch(void* const* d_in, const int* in_sizes, int n_in,
                              void* d_out, int out_size)
{
    const float* inputs  = (const float*)d_in[0];
    const float* state   = (const float*)d_in[1];
    const float* kernels = (const float*)d_in[2];
    const float* biases  = (const float*)d_in[3];
    const float* projs   = (const float*)d_in[4];
    const float* gamma   = (const float*)d_in[5];
    const float* beta    = (const float*)d_in[6];
    const float* convw   = (const float*)d_in[7];
    const float* convb   = (const float*)d_in[8];
    float* out = (float*)d_out;

    float *xg, *bufA, *bufB, *convA, *hs, *c, *h, *s;
    cudaGetSymbolAddress((void**)&xg,    g_xg);
    cudaGetSymbolAddress((void**)&bufA,  g_bufA);
    cudaGetSymbolAddress((void**)&bufB,  g_bufB);
    cudaGetSymbolAddress((void**)&convA, g_convA);
    cudaGetSymbolAddress((void**)&hs,    g_hs);
    cudaGetSymbolAddress((void**)&c,     g_c);
    cudaGetSymbolAddress((void**)&h,     g_h);
    cudaGetSymbolAddress((void**)&s,     g_s);

    init_state<<<128, 256>>>(state, c, h);

    const float* x = inputs;
    int T = T0;
    for (int l = 0; l < NL; l++) {
        const float* Wx = kernels + (size_t)l * 2 * PP * G4;
        const float* Wh = Wx + (size_t)PP * G4;
        const float* bi = biases + (size_t)l * G4;
        const float* pr = projs + (size_t)l * DD * PP;
        const int M = BB * T;

        dim3 g1(G4 / GBN, (M + GBM - 1) / GBM);
        gemm_tf32<<<g1, 256>>>(x, Wx, bi, xg, M, G4, PP);

        reset_bar<<<1, 1>>>();
        lstm_persist<<<NBLK, 512>>>(xg, Wh, pr, c, h, s, hs, T);

        float* lnout = (l == 0) ? bufA : (l == 1) ? bufB : (l == 2) ? bufA : out;
        ln_kernel<<<BB * T, 256>>>(hs, gamma, beta, lnout);

        if (l == 1) {
            build_convA<<<(BB * TR * DD + 255) / 256, 256>>>(bufB, convA);
            dim3 g2(PP / GBN, (BB * TR + GBM - 1) / GBM);
            gemm_tf32<<<g2, 256>>>(convA, convw, convb, bufA, BB * TR, PP, DD);
            T = TR;
            x = bufA;
        } else {
            x = bufA;
        }
    }

    write_tail<<<128, 256>>>(c, h, out);
}

// round 4
// speedup vs baseline: 1.2602x; 1.2602x over previous
#include <cuda_runtime.h>
#include <cuda_bf16.h>
#include <math.h>

// ---------------- problem constants ----------------
#define BB 16
#define T0 512
#define TR 511
#define PP 1024
#define DD 2048
#define G4 8192   // 4*D
#define NL 4
#define NBLK 128

// ---------------- scratch (device globals; no allocation allowed) ----------------
__device__ __align__(16) float g_xg[(size_t)BB * T0 * G4];      // 256 MB
__device__ __align__(16) float g_bufA[(size_t)BB * T0 * PP];    // 32 MB
__device__ __align__(16) float g_bufB[(size_t)BB * T0 * PP];    // 32 MB
__device__ __align__(16) float g_convA[(size_t)BB * T0 * DD];   // 64 MB
__device__ __align__(16) float g_hs[(size_t)BB * T0 * PP];      // 32 MB
__device__ __align__(16) uint4 g_whp[(size_t)1024 * 64 * 32];   // 32 MB packed Wh fragments
__device__ __align__(16) uint4 g_projp[(size_t)128 * 128 * 32]; // 8 MB packed proj fragments
__device__ __align__(16) float g_c[BB * DD];
__device__ __align__(16) float g_h[BB * PP];
__device__ __align__(16) float g_s[BB * DD];
__device__ unsigned int g_bar;

// ================= bf16 split helpers =================
__device__ __forceinline__ void bsplit2(float a, float b, unsigned& hi, unsigned& lo) {
    __nv_bfloat162 h2 = __floats2bfloat162_rn(a, b);
    float ra = a - __bfloat162float(h2.x);
    float rb = b - __bfloat162float(h2.y);
    __nv_bfloat162 l2 = __floats2bfloat162_rn(ra, rb);
    hi = *reinterpret_cast<unsigned*>(&h2);
    lo = *reinterpret_cast<unsigned*>(&l2);
}

__device__ __forceinline__ void mma_bf16(float* c, const unsigned* a, const unsigned* b) {
    asm volatile(
        "mma.sync.aligned.m16n8k16.row.col.f32.bf16.bf16.f32 "
        "{%0,%1,%2,%3},{%4,%5,%6,%7},{%8,%9},{%0,%1,%2,%3};"
        : "+f"(c[0]), "+f"(c[1]), "+f"(c[2]), "+f"(c[3])
        : "r"(a[0]), "r"(a[1]), "r"(a[2]), "r"(a[3]), "r"(b[0]), "r"(b[1]));
}

// ================= tf32 helpers (GEMM path, unchanged) =================
__device__ __forceinline__ unsigned f2tf32(float x) {
    unsigned r;
    asm("cvt.rna.tf32.f32 %0, %1;" : "=r"(r) : "f"(x));
    return r;
}
__device__ __forceinline__ void split_tf32(float x, unsigned& hi, unsigned& lo) {
    hi = f2tf32(x);
    lo = f2tf32(x - __uint_as_float(hi));
}
__device__ __forceinline__ void mma_tf32(float* c, const unsigned* a, const unsigned* b) {
    asm volatile(
        "mma.sync.aligned.m16n8k8.row.col.f32.tf32.tf32.f32 "
        "{%0,%1,%2,%3},{%4,%5,%6,%7},{%8,%9},{%0,%1,%2,%3};"
        : "+f"(c[0]), "+f"(c[1]), "+f"(c[2]), "+f"(c[3])
        : "r"(a[0]), "r"(a[1]), "r"(a[2]), "r"(a[3]), "r"(b[0]), "r"(b[1]));
}

// ================= weight fragment packer =================
// W: K x N row-major. Output: [ntile][kstep][lane] uint4 {b0_hi,b1_hi,b0_lo,b1_lo}.
// Fragment (m16n8k16 B, col-major): lane l (g=l>>2, t=l&3):
//   b0 = { B[k0+2t][g], B[k0+2t+1][g] }, b1 = { B[k0+8+2t][g], B[k0+9+2t][g] }.
__global__ __launch_bounds__(256) void pack_frag(
    const float* __restrict__ W, uint4* __restrict__ out, int N, int ksteps)
{
    __shared__ float tile[8][16][8];
    const int wlocal = threadIdx.x >> 5;
    const int lane = threadIdx.x & 31;
    const int wglob = blockIdx.x * 8 + wlocal;
    const int nt = wglob / ksteps;
    const int ks = wglob - nt * ksteps;

    // coalesced-ish tile load: lane covers 4 consecutive elems of the 16x8 tile
    {
        const int r = lane >> 1;
        const int cb = (lane & 1) * 4;
        float4 v = *(const float4*)&W[(size_t)(ks * 16 + r) * N + nt * 8 + cb];
        tile[wlocal][r][cb + 0] = v.x;
        tile[wlocal][r][cb + 1] = v.y;
        tile[wlocal][r][cb + 2] = v.z;
        tile[wlocal][r][cb + 3] = v.w;
    }
    __syncwarp();

    const int g = lane >> 2;
    const int t = lane & 3;
    float v00 = tile[wlocal][2 * t][g];
    float v01 = tile[wlocal][2 * t + 1][g];
    float v10 = tile[wlocal][2 * t + 8][g];
    float v11 = tile[wlocal][2 * t + 9][g];
    uint4 o;
    bsplit2(v00, v01, o.x, o.z);
    bsplit2(v10, v11, o.y, o.w);
    out[((size_t)(nt * ksteps + ks)) * 32 + lane] = o;
}

// ================= split-tf32 GEMM (unchanged from R3) =================
#define GBM 128
#define GBN 128
#define GBK 16
#define ASTR (GBM + 8)
#define BSTR (GBN + 8)

__global__ __launch_bounds__(256) void gemm_tf32(
    const float* __restrict__ A, const float* __restrict__ Bw,
    const float* __restrict__ bias, float* __restrict__ C,
    int M, int N, int K)
{
    __shared__ float As[GBK][ASTR];
    __shared__ float Bs[GBK][BSTR];

    const int bm = blockIdx.y * GBM;
    const int bn = blockIdx.x * GBN;
    const int tid = threadIdx.x;
    const int lane = tid & 31;
    const int wid = tid >> 5;
    const int wm = (wid >> 2) * 64;
    const int wn = (wid & 3) * 32;
    const int lg = lane >> 2;
    const int lk = lane & 3;

    float acc[4][4][4];
#pragma unroll
    for (int mt = 0; mt < 4; mt++)
#pragma unroll
        for (int nt = 0; nt < 4; nt++)
#pragma unroll
            for (int r = 0; r < 4; r++) acc[mt][nt][r] = 0.0f;

    for (int k0 = 0; k0 < K; k0 += GBK) {
#pragma unroll
        for (int it = 0; it < 2; it++) {
            int f = tid + it * 256;
            int r = f >> 2;
            int kq = (f & 3) * 4;
            float4 v = make_float4(0.f, 0.f, 0.f, 0.f);
            if (bm + r < M) v = *(const float4*)&A[(size_t)(bm + r) * K + k0 + kq];
            As[kq + 0][r] = v.x;
            As[kq + 1][r] = v.y;
            As[kq + 2][r] = v.z;
            As[kq + 3][r] = v.w;
        }
#pragma unroll
        for (int it = 0; it < 2; it++) {
            int f = tid + it * 256;
            int r = f >> 5;
            int nq = (f & 31) * 4;
            float4 v = *(const float4*)&Bw[(size_t)(k0 + r) * N + bn + nq];
            *(float4*)&Bs[r][nq] = v;
        }
        __syncthreads();

#pragma unroll
        for (int kk = 0; kk < GBK; kk += 8) {
            unsigned ah[4][4], al[4][4], bh[4][2], bl[4][2];
#pragma unroll
            for (int mt = 0; mt < 4; mt++) {
                int row = wm + mt * 16 + lg;
                float a0 = As[kk + lk][row];
                float a1 = As[kk + lk][row + 8];
                float a2 = As[kk + 4 + lk][row];
                float a3 = As[kk + 4 + lk][row + 8];
                split_tf32(a0, ah[mt][0], al[mt][0]);
                split_tf32(a1, ah[mt][1], al[mt][1]);
                split_tf32(a2, ah[mt][2], al[mt][2]);
                split_tf32(a3, ah[mt][3], al[mt][3]);
            }
#pragma unroll
            for (int nt = 0; nt < 4; nt++) {
                int col = wn + nt * 8 + lg;
                float b0 = Bs[kk + lk][col];
                float b1 = Bs[kk + 4 + lk][col];
                split_tf32(b0, bh[nt][0], bl[nt][0]);
                split_tf32(b1, bh[nt][1], bl[nt][1]);
            }
#pragma unroll
            for (int mt = 0; mt < 4; mt++)
#pragma unroll
                for (int nt = 0; nt < 4; nt++) {
                    mma_tf32(acc[mt][nt], ah[mt], bh[nt]);
                    mma_tf32(acc[mt][nt], ah[mt], bl[nt]);
                    mma_tf32(acc[mt][nt], al[mt], bh[nt]);
                }
        }
        __syncthreads();
    }

#pragma unroll
    for (int mt = 0; mt < 4; mt++) {
#pragma unroll
        for (int nt = 0; nt < 4; nt++) {
            int row0 = bm + wm + mt * 16 + lg;
            int col0 = bn + wn + nt * 8 + lk * 2;
            float b0 = bias[col0], b1 = bias[col0 + 1];
            if (row0 < M) {
                float2 v = make_float2(acc[mt][nt][0] + b0, acc[mt][nt][1] + b1);
                *(float2*)&C[(size_t)row0 * N + col0] = v;
            }
            if (row0 + 8 < M) {
                float2 v = make_float2(acc[mt][nt][2] + b0, acc[mt][nt][3] + b1);
                *(float2*)&C[(size_t)(row0 + 8) * N + col0] = v;
            }
        }
    }
}

// ================= persistent LSTM layer kernel (tensor-core) =================
__device__ __forceinline__ void grid_barrier(unsigned target) {
    __syncthreads();
    __threadfence();
    if (threadIdx.x == 0) {
        atomicAdd(&g_bar, 1u);
        while (*(volatile unsigned int*)&g_bar < target) {
            __nanosleep(40);
        }
    }
    __syncthreads();
}

// dynamic smem: frag region 128 KB (uint4[8192]) + red region 8 KB (float[2048])
#define SMEM_BYTES (136 * 1024)

__global__ __launch_bounds__(512, 1) void lstm_persist(
    const float* __restrict__ xg,       // (B*T, 8192)
    const uint4* __restrict__ whp,      // packed Wh fragments [1024][64][32]
    const uint4* __restrict__ projp,    // packed proj fragments [128][128][32]
    float* __restrict__ c,              // (16, 2048)
    float* __restrict__ h,              // (16, 1024)
    float* __restrict__ s,              // (16, 2048)
    float* __restrict__ hs,             // (B*T, 1024)
    int T)
{
    extern __shared__ __align__(16) char dynsmem[];
    uint4* frag = (uint4*)dynsmem;                      // phase A: 4096 uint4; phase B: 8192 uint4
    float* red  = (float*)(dynsmem + 128 * 1024);       // 2048 floats
    float* gbuf = red + 1024;                           // phase A gate buffer (1024 floats)

    const int tid  = threadIdx.x;
    const int lane = tid & 31;
    const int warp = tid >> 5;        // 0..15
    const int bid  = blockIdx.x;
    const int d0   = bid * 16;        // this block's d-range
    const int p0   = bid * 8;         // this block's p-range

    // phase A warp mapping
    const int subA = warp & 7;
    const int khA  = warp >> 3;       // k-half: 0 -> k[0,512), 1 -> k[512,1024)
    const int gateA = subA >> 1;
    const int halfA = subA & 1;
    const int ntA  = gateA * 256 + bid * 2 + halfA;
    const uint4* wpA = whp + ((size_t)(ntA * 64 + khA * 32)) * 32 + lane;

    const int lg = lane >> 2;
    const int lt = lane & 3;

    unsigned epoch = 0;

    for (int t = 0; t < T; t++) {
        // ---- prefetch xg + c for cell update (DRAM latency hidden behind mma loop) ----
        float xgv[4], cold;
        {
            const int b  = tid >> 4;
            const int dd = tid & 15;
            if (tid < 256) {
                const size_t xrow = ((size_t)(b * T + t)) * G4;
                xgv[0] = xg[xrow + 0 * DD + d0 + dd];
                xgv[1] = xg[xrow + 1 * DD + d0 + dd];
                xgv[2] = xg[xrow + 2 * DD + d0 + dd];
                xgv[3] = xg[xrow + 3 * DD + d0 + dd];
                cold = c[b * DD + d0 + dd];
            }
        }

        // ---- build h A-fragments in smem (64 ksteps x 32 lanes, hi+lo) ----
#pragma unroll
        for (int i = 0; i < 4; i++) {
            const int e  = tid + i * 512;      // 0..2047
            const int ks = e >> 5;
            const int l  = e & 31;
            const int g  = l >> 2;
            const int tt = l & 3;
            const int k0 = ks * 16;
            float2 p00 = __ldcg((const float2*)&h[g * PP + k0 + 2 * tt]);
            float2 p01 = __ldcg((const float2*)&h[(g + 8) * PP + k0 + 2 * tt]);
            float2 p10 = __ldcg((const float2*)&h[g * PP + k0 + 8 + 2 * tt]);
            float2 p11 = __ldcg((const float2*)&h[(g + 8) * PP + k0 + 8 + 2 * tt]);
            uint4 fh, fl;
            bsplit2(p00.x, p00.y, fh.x, fl.x);
            bsplit2(p01.x, p01.y, fh.y, fl.y);
            bsplit2(p10.x, p10.y, fh.z, fl.z);
            bsplit2(p11.x, p11.y, fh.w, fl.w);
            frag[e * 2 + 0] = fh;
            frag[e * 2 + 1] = fl;
        }
        __syncthreads();

        // ---- phase A mma: gates = h @ Wh slice ----
        float acc[4] = {0.f, 0.f, 0.f, 0.f};
        {
            const uint4* ap = frag + (size_t)(khA * 32) * 64 + lane * 2;
#pragma unroll 4
            for (int ks = 0; ks < 32; ks++) {
                uint4 bfrag = wpA[(size_t)ks * 32];
                uint4 ah = ap[(size_t)ks * 64];
                uint4 al = ap[(size_t)ks * 64 + 1];
                unsigned bh[2] = {bfrag.x, bfrag.y};
                unsigned bl[2] = {bfrag.z, bfrag.w};
                mma_bf16(acc, &ah.x, bh);
                mma_bf16(acc, &ah.x, bl);
                mma_bf16(acc, &al.x, bh);
            }
        }

        // ---- reduce the two k-halves ----
        if (khA == 1) {
#pragma unroll
            for (int r = 0; r < 4; r++) red[(subA * 32 + lane) * 4 + r] = acc[r];
        }
        __syncthreads();
        if (khA == 0) {
#pragma unroll
            for (int r = 0; r < 4; r++) acc[r] += red[(subA * 32 + lane) * 4 + r];
            // scatter into gate buffer gbuf[b][dd][gate]
            const int ddb = halfA * 8 + 2 * lt;
            gbuf[(lg * 16 + ddb) * 4 + gateA]           = acc[0];
            gbuf[(lg * 16 + ddb + 1) * 4 + gateA]       = acc[1];
            gbuf[((lg + 8) * 16 + ddb) * 4 + gateA]     = acc[2];
            gbuf[((lg + 8) * 16 + ddb + 1) * 4 + gateA] = acc[3];
        }
        __syncthreads();

        // ---- cell update ----
        if (tid < 256) {
            const int b  = tid >> 4;
            const int dd = tid & 15;
            const int d  = d0 + dd;
            float4 gv = *(float4*)&gbuf[(b * 16 + dd) * 4];
            float gi = gv.x + xgv[0];
            float gj = gv.y + xgv[1];
            float gf = gv.z + xgv[2];
            float go = gv.w + xgv[3];
            float si = 1.0f / (1.0f + expf(-gi));
            float sf = 1.0f / (1.0f + expf(-(gf + 1.0f)));
            float so = 1.0f / (1.0f + expf(-go));
            float cn = sf * cold + si * tanhf(gj);
            c[b * DD + d] = cn;
            s[b * DD + d] = so * tanhf(cn);
        }

        epoch++;
        grid_barrier(epoch * NBLK);

        // ---- build s A-fragments (128 ksteps x 32 lanes, hi+lo) ----
#pragma unroll
        for (int i = 0; i < 8; i++) {
            const int e  = tid + i * 512;      // 0..4095
            const int ks = e >> 5;
            const int l  = e & 31;
            const int g  = l >> 2;
            const int tt = l & 3;
            const int k0 = ks * 16;
            float2 p00 = __ldcg((const float2*)&s[g * DD + k0 + 2 * tt]);
            float2 p01 = __ldcg((const float2*)&s[(g + 8) * DD + k0 + 2 * tt]);
            float2 p10 = __ldcg((const float2*)&s[g * DD + k0 + 8 + 2 * tt]);
            float2 p11 = __ldcg((const float2*)&s[(g + 8) * DD + k0 + 8 + 2 * tt]);
            uint4 fh, fl;
            bsplit2(p00.x, p00.y, fh.x, fl.x);
            bsplit2(p01.x, p01.y, fh.y, fl.y);
            bsplit2(p10.x, p10.y, fh.z, fl.z);
            bsplit2(p11.x, p11.y, fh.w, fl.w);
            frag[e * 2 + 0] = fh;
            frag[e * 2 + 1] = fl;
        }
        __syncthreads();

        // ---- phase B mma: h = s @ proj slice (warp w covers ksteps [8w, 8w+8)) ----
        float accp[4] = {0.f, 0.f, 0.f, 0.f};
        {
            const uint4* pp = projp + ((size_t)(bid * 128 + warp * 8)) * 32 + lane;
            const uint4* ap = frag + (size_t)(warp * 8) * 64 + lane * 2;
#pragma unroll
            for (int ks = 0; ks < 8; ks++) {
                uint4 bfrag = pp[(size_t)ks * 32];
                uint4 ah = ap[(size_t)ks * 64];
                uint4 al = ap[(size_t)ks * 64 + 1];
                unsigned bh[2] = {bfrag.x, bfrag.y};
                unsigned bl[2] = {bfrag.z, bfrag.w};
                mma_bf16(accp, &ah.x, bh);
                mma_bf16(accp, &ah.x, bl);
                mma_bf16(accp, &al.x, bh);
            }
        }
#pragma unroll
        for (int r = 0; r < 4; r++) red[(warp * 32 + lane) * 4 + r] = accp[r];
        __syncthreads();

        if (tid < 128) {
            const int b = tid >> 3;
            const int p = tid & 7;
            const int rl = (b & 7) * 4 + (p >> 1);
            const int rr = (b < 8) ? (p & 1) : (2 + (p & 1));
            float v = 0.0f;
#pragma unroll
            for (int w = 0; w < 16; w++) v += red[(w * 32 + rl) * 4 + rr];
            h[b * PP + p0 + p] = v;
            hs[((size_t)(b * T + t)) * PP + p0 + p] = v;
        }

        epoch++;
        grid_barrier(epoch * NBLK);
    }
}

// ================= LayerNorm over rows of 1024 =================
__global__ __launch_bounds__(256) void ln_kernel(
    const float* __restrict__ x, const float* __restrict__ gam,
    const float* __restrict__ bet, float* __restrict__ y)
{
    __shared__ float sred[256];
    const size_t r = blockIdx.x;
    const float* xr = x + r * PP;
    const int tid = threadIdx.x;

    float v[4];
#pragma unroll
    for (int i = 0; i < 4; i++) v[i] = xr[tid + i * 256];
    float sm = v[0] + v[1] + v[2] + v[3];
    sred[tid] = sm;
    __syncthreads();
    for (int off = 128; off > 0; off >>= 1) {
        if (tid < off) sred[tid] += sred[tid + off];
        __syncthreads();
    }
    float mean = sred[0] * (1.0f / 1024.0f);
    __syncthreads();

    float q = 0.0f;
#pragma unroll
    for (int i = 0; i < 4; i++) { float d = v[i] - mean; q += d * d; }
    sred[tid] = q;
    __syncthreads();
    for (int off = 128; off > 0; off >>= 1) {
        if (tid < off) sred[tid] += sred[tid + off];
        __syncthreads();
    }
    float inv = rsqrtf(sred[0] * (1.0f / 1024.0f) + 1e-3f);

#pragma unroll
    for (int i = 0; i < 4; i++) {
        int col = tid + i * 256;
        y[r * PP + col] = (v[i] - mean) * inv * gam[col] + bet[col];
    }
}

// ================= conv im2col =================
__global__ __launch_bounds__(256) void build_convA(
    const float* __restrict__ ln, float* __restrict__ Acat)
{
    size_t idx = (size_t)blockIdx.x * 256 + threadIdx.x;
    if (idx >= (size_t)BB * TR * DD) return;
    int m = (int)(idx >> 11);
    int k = (int)(idx & 2047);
    int b = m / TR;
    int t = m - b * TR;
    int w = k >> 10;
    int p = k & 1023;
    Acat[idx] = ln[((size_t)(b * T0 + t + w)) * PP + p];
}

// ================= init / reset / tail =================
__global__ __launch_bounds__(256) void init_state(
    const float* __restrict__ state, float* __restrict__ c, float* __restrict__ h)
{
    int i = blockIdx.x * 256 + threadIdx.x;
    if (i < BB * DD) c[i] = state[i];
    if (i < BB * PP) {
        int b = i >> 10, p = i & 1023;
        h[i] = state[BB * DD + b * DD + p];
    }
}

__global__ void reset_bar() { g_bar = 0u; }

__global__ __launch_bounds__(256) void write_tail(
    const float* __restrict__ c, const float* __restrict__ h, float* __restrict__ out)
{
    const size_t base = (size_t)BB * TR * PP;
    int i = blockIdx.x * 256 + threadIdx.x;
    if (i < BB * DD) out[base + i] = c[i];
    if (i < BB * PP) out[base + BB * DD + i] = h[i];
}

// ================= orchestration =================
extern "C" void kernel_launch(void* const* d_in, const int* in_sizes, int n_in,
                              void* d_out, int out_size)
{
    const float* inputs  = (const float*)d_in[0];
    const float* state   = (const float*)d_in[1];
    const float* kernels = (const float*)d_in[2];
    const float* biases  = (const float*)d_in[3];
    const float* projs   = (const float*)d_in[4];
    const float* gamma   = (const float*)d_in[5];
    const float* beta    = (const float*)d_in[6];
    const float* convw   = (const float*)d_in[7];
    const float* convb   = (const float*)d_in[8];
    float* out = (float*)d_out;

    float *xg, *bufA, *bufB, *convA, *hs, *c, *h, *s;
    uint4 *whp, *projp;
    cudaGetSymbolAddress((void**)&xg,    g_xg);
    cudaGetSymbolAddress((void**)&bufA,  g_bufA);
    cudaGetSymbolAddress((void**)&bufB,  g_bufB);
    cudaGetSymbolAddress((void**)&convA, g_convA);
    cudaGetSymbolAddress((void**)&hs,    g_hs);
    cudaGetSymbolAddress((void**)&whp,   g_whp);
    cudaGetSymbolAddress((void**)&projp, g_projp);
    cudaGetSymbolAddress((void**)&c,     g_c);
    cudaGetSymbolAddress((void**)&h,     g_h);
    cudaGetSymbolAddress((void**)&s,     g_s);

    static int smem_set = 0;
    if (!smem_set) {
        cudaFuncSetAttribute(lstm_persist, cudaFuncAttributeMaxDynamicSharedMemorySize, SMEM_BYTES);
        smem_set = 1;
    }

    init_state<<<128, 256>>>(state, c, h);

    const float* x = inputs;
    int T = T0;
    for (int l = 0; l < NL; l++) {
        const float* Wx = kernels + (size_t)l * 2 * PP * G4;
        const float* Wh = Wx + (size_t)PP * G4;
        const float* bi = biases + (size_t)l * G4;
        const float* pr = projs + (size_t)l * DD * PP;
        const int M = BB * T;

        // pack recurrent weights for this layer (fragment order, bf16 hi/lo)
        pack_frag<<<(1024 * 64) / 8, 256>>>(Wh, whp, G4, 64);     // Wh: 1024x8192, ksteps=64
        pack_frag<<<(128 * 128) / 8, 256>>>(pr, projp, PP, 128);  // proj: 2048x1024, ksteps=128

        dim3 g1(G4 / GBN, (M + GBM - 1) / GBM);
        gemm_tf32<<<g1, 256>>>(x, Wx, bi, xg, M, G4, PP);

        reset_bar<<<1, 1>>>();
        lstm_persist<<<NBLK, 512, SMEM_BYTES>>>(xg, whp, projp, c, h, s, hs, T);

        float* lnout = (l == 0) ? bufA : (l == 1) ? bufB : (l == 2) ? bufA : out;
        ln_kernel<<<BB * T, 256>>>(hs, gamma, beta, lnout);

        if (l == 1) {
            build_convA<<<(BB * TR * DD + 255) / 256, 256>>>(bufB, convA);
            dim3 g2(PP / GBN, (BB * TR + GBM - 1) / GBM);
            gemm_tf32<<<g2, 256>>>(convA, convw, convb, bufA, BB * TR, PP, DD);
            T = TR;
            x = bufA;
        } else {
            x = bufA;
        }
    }

    write_tail<<<128, 256>>>(c, h, out);
}

// round 5
// speedup vs baseline: 1.2614x; 1.0010x over previous
#include <cuda_runtime.h>
#include <cuda_bf16.h>
#include <math.h>

// ---------------- problem constants ----------------
#define BB 16
#define T0 512
#define TR 511
#define PP 1024
#define DD 2048
#define G4 8192   // 4*D
#define NL 4
#define NBLK 128

// ---------------- scratch (device globals; no allocation allowed) ----------------
__device__ __align__(16) float g_xg[(size_t)BB * T0 * G4];      // 256 MB
__device__ __align__(16) float g_bufA[(size_t)BB * T0 * PP];    // 32 MB
__device__ __align__(16) float g_bufB[(size_t)BB * T0 * PP];    // 32 MB
__device__ __align__(16) float g_convA[(size_t)BB * T0 * DD];   // 64 MB
__device__ __align__(16) float g_hs[(size_t)BB * T0 * PP];      // 32 MB
__device__ __align__(16) uint4 g_whp[(size_t)1024 * 64 * 32];   // 32 MB packed Wh fragments
__device__ __align__(16) uint4 g_projp[(size_t)128 * 128 * 32]; // 8 MB packed proj fragments
__device__ __align__(16) float g_c[BB * DD];
__device__ __align__(16) float g_h[BB * PP];
__device__ __align__(16) float g_s[BB * DD];
__device__ unsigned int g_bar;

// ================= bf16 split helpers =================
__device__ __forceinline__ void bsplit2(float a, float b, unsigned& hi, unsigned& lo) {
    __nv_bfloat162 h2 = __floats2bfloat162_rn(a, b);
    float ra = a - __bfloat162float(h2.x);
    float rb = b - __bfloat162float(h2.y);
    __nv_bfloat162 l2 = __floats2bfloat162_rn(ra, rb);
    hi = *reinterpret_cast<unsigned*>(&h2);
    lo = *reinterpret_cast<unsigned*>(&l2);
}

__device__ __forceinline__ void mma_bf16(float* c, const unsigned* a, const unsigned* b) {
    asm volatile(
        "mma.sync.aligned.m16n8k16.row.col.f32.bf16.bf16.f32 "
        "{%0,%1,%2,%3},{%4,%5,%6,%7},{%8,%9},{%0,%1,%2,%3};"
        : "+f"(c[0]), "+f"(c[1]), "+f"(c[2]), "+f"(c[3])
        : "r"(a[0]), "r"(a[1]), "r"(a[2]), "r"(a[3]), "r"(b[0]), "r"(b[1]));
}

// ================= tf32 helpers (GEMM path, unchanged) =================
__device__ __forceinline__ unsigned f2tf32(float x) {
    unsigned r;
    asm("cvt.rna.tf32.f32 %0, %1;" : "=r"(r) : "f"(x));
    return r;
}
__device__ __forceinline__ void split_tf32(float x, unsigned& hi, unsigned& lo) {
    hi = f2tf32(x);
    lo = f2tf32(x - __uint_as_float(hi));
}
__device__ __forceinline__ void mma_tf32(float* c, const unsigned* a, const unsigned* b) {
    asm volatile(
        "mma.sync.aligned.m16n8k8.row.col.f32.tf32.tf32.f32 "
        "{%0,%1,%2,%3},{%4,%5,%6,%7},{%8,%9},{%0,%1,%2,%3};"
        : "+f"(c[0]), "+f"(c[1]), "+f"(c[2]), "+f"(c[3])
        : "r"(a[0]), "r"(a[1]), "r"(a[2]), "r"(a[3]), "r"(b[0]), "r"(b[1]));
}

// ================= weight fragment packer =================
// W: K x N row-major. Output: [ntile][kstep][lane] uint4 {b0_hi,b1_hi,b0_lo,b1_lo}.
// Fragment (m16n8k16 B, col-major): lane l (g=l>>2, t=l&3):
//   b0 = { B[k0+2t][g], B[k0+2t+1][g] }, b1 = { B[k0+8+2t][g], B[k0+9+2t][g] }.
__global__ __launch_bounds__(256) void pack_frag(
    const float* __restrict__ W, uint4* __restrict__ out, int N, int ksteps)
{
    __shared__ float tile[8][16][8];
    const int wlocal = threadIdx.x >> 5;
    const int lane = threadIdx.x & 31;
    const int wglob = blockIdx.x * 8 + wlocal;
    const int nt = wglob / ksteps;
    const int ks = wglob - nt * ksteps;

    // coalesced-ish tile load: lane covers 4 consecutive elems of the 16x8 tile
    {
        const int r = lane >> 1;
        const int cb = (lane & 1) * 4;
        float4 v = *(const float4*)&W[(size_t)(ks * 16 + r) * N + nt * 8 + cb];
        tile[wlocal][r][cb + 0] = v.x;
        tile[wlocal][r][cb + 1] = v.y;
        tile[wlocal][r][cb + 2] = v.z;
        tile[wlocal][r][cb + 3] = v.w;
    }
    __syncwarp();

    const int g = lane >> 2;
    const int t = lane & 3;
    float v00 = tile[wlocal][2 * t][g];
    float v01 = tile[wlocal][2 * t + 1][g];
    float v10 = tile[wlocal][2 * t + 8][g];
    float v11 = tile[wlocal][2 * t + 9][g];
    uint4 o;
    bsplit2(v00, v01, o.x, o.z);
    bsplit2(v10, v11, o.y, o.w);
    out[((size_t)(nt * ksteps + ks)) * 32 + lane] = o;
}

// ================= split-tf32 GEMM (unchanged from R3) =================
#define GBM 128
#define GBN 128
#define GBK 16
#define ASTR (GBM + 8)
#define BSTR (GBN + 8)

__global__ __launch_bounds__(256) void gemm_tf32(
    const float* __restrict__ A, const float* __restrict__ Bw,
    const float* __restrict__ bias, float* __restrict__ C,
    int M, int N, int K)
{
    __shared__ float As[GBK][ASTR];
    __shared__ float Bs[GBK][BSTR];

    const int bm = blockIdx.y * GBM;
    const int bn = blockIdx.x * GBN;
    const int tid = threadIdx.x;
    const int lane = tid & 31;
    const int wid = tid >> 5;
    const int wm = (wid >> 2) * 64;
    const int wn = (wid & 3) * 32;
    const int lg = lane >> 2;
    const int lk = lane & 3;

    float acc[4][4][4];
#pragma unroll
    for (int mt = 0; mt < 4; mt++)
#pragma unroll
        for (int nt = 0; nt < 4; nt++)
#pragma unroll
            for (int r = 0; r < 4; r++) acc[mt][nt][r] = 0.0f;

    for (int k0 = 0; k0 < K; k0 += GBK) {
#pragma unroll
        for (int it = 0; it < 2; it++) {
            int f = tid + it * 256;
            int r = f >> 2;
            int kq = (f & 3) * 4;
            float4 v = make_float4(0.f, 0.f, 0.f, 0.f);
            if (bm + r < M) v = *(const float4*)&A[(size_t)(bm + r) * K + k0 + kq];
            As[kq + 0][r] = v.x;
            As[kq + 1][r] = v.y;
            As[kq + 2][r] = v.z;
            As[kq + 3][r] = v.w;
        }
#pragma unroll
        for (int it = 0; it < 2; it++) {
            int f = tid + it * 256;
            int r = f >> 5;
            int nq = (f & 31) * 4;
            float4 v = *(const float4*)&Bw[(size_t)(k0 + r) * N + bn + nq];
            *(float4*)&Bs[r][nq] = v;
        }
        __syncthreads();

#pragma unroll
        for (int kk = 0; kk < GBK; kk += 8) {
            unsigned ah[4][4], al[4][4], bh[4][2], bl[4][2];
#pragma unroll
            for (int mt = 0; mt < 4; mt++) {
                int row = wm + mt * 16 + lg;
                float a0 = As[kk + lk][row];
                float a1 = As[kk + lk][row + 8];
                float a2 = As[kk + 4 + lk][row];
                float a3 = As[kk + 4 + lk][row + 8];
                split_tf32(a0, ah[mt][0], al[mt][0]);
                split_tf32(a1, ah[mt][1], al[mt][1]);
                split_tf32(a2, ah[mt][2], al[mt][2]);
                split_tf32(a3, ah[mt][3], al[mt][3]);
            }
#pragma unroll
            for (int nt = 0; nt < 4; nt++) {
                int col = wn + nt * 8 + lg;
                float b0 = Bs[kk + lk][col];
                float b1 = Bs[kk + 4 + lk][col];
                split_tf32(b0, bh[nt][0], bl[nt][0]);
                split_tf32(b1, bh[nt][1], bl[nt][1]);
            }
#pragma unroll
            for (int mt = 0; mt < 4; mt++)
#pragma unroll
                for (int nt = 0; nt < 4; nt++) {
                    mma_tf32(acc[mt][nt], ah[mt], bh[nt]);
                    mma_tf32(acc[mt][nt], ah[mt], bl[nt]);
                    mma_tf32(acc[mt][nt], al[mt], bh[nt]);
                }
        }
        __syncthreads();
    }

#pragma unroll
    for (int mt = 0; mt < 4; mt++) {
#pragma unroll
        for (int nt = 0; nt < 4; nt++) {
            int row0 = bm + wm + mt * 16 + lg;
            int col0 = bn + wn + nt * 8 + lk * 2;
            float b0 = bias[col0], b1 = bias[col0 + 1];
            if (row0 < M) {
                float2 v = make_float2(acc[mt][nt][0] + b0, acc[mt][nt][1] + b1);
                *(float2*)&C[(size_t)row0 * N + col0] = v;
            }
            if (row0 + 8 < M) {
                float2 v = make_float2(acc[mt][nt][2] + b0, acc[mt][nt][3] + b1);
                *(float2*)&C[(size_t)(row0 + 8) * N + col0] = v;
            }
        }
    }
}

// ================= persistent LSTM layer kernel (tensor-core) =================
__device__ __forceinline__ void grid_barrier(unsigned target) {
    __syncthreads();
    __threadfence();
    if (threadIdx.x == 0) {
        atomicAdd(&g_bar, 1u);
        while (*(volatile unsigned int*)&g_bar < target) {
            __nanosleep(40);
        }
    }
    __syncthreads();
}

// dynamic smem: frag region 128 KB (uint4[8192]) + red region 8 KB (float[2048])
#define SMEM_BYTES (136 * 1024)

__global__ __launch_bounds__(512, 1) void lstm_persist(
    const float* __restrict__ xg,       // (B*T, 8192)
    const uint4* __restrict__ whp,      // packed Wh fragments [1024][64][32]
    const uint4* __restrict__ projp,    // packed proj fragments [128][128][32]
    float* __restrict__ c,              // (16, 2048)
    float* __restrict__ h,              // (16, 1024)
    float* __restrict__ s,              // (16, 2048)
    float* __restrict__ hs,             // (B*T, 1024)
    int T)
{
    extern __shared__ __align__(16) char dynsmem[];
    uint4* frag = (uint4*)dynsmem;                      // phase A: 4096 uint4; phase B: 8192 uint4
    float* red  = (float*)(dynsmem + 128 * 1024);       // 2048 floats
    float* gbuf = red + 1024;                           // phase A gate buffer (1024 floats)

    const int tid  = threadIdx.x;
    const int lane = tid & 31;
    const int warp = tid >> 5;        // 0..15
    const int bid  = blockIdx.x;
    const int d0   = bid * 16;        // this block's d-range
    const int p0   = bid * 8;         // this block's p-range

    // phase A warp mapping
    const int subA = warp & 7;
    const int khA  = warp >> 3;       // k-half: 0 -> k[0,512), 1 -> k[512,1024)
    const int gateA = subA >> 1;
    const int halfA = subA & 1;
    const int ntA  = gateA * 256 + bid * 2 + halfA;
    const uint4* wpA = whp + ((size_t)(ntA * 64 + khA * 32)) * 32 + lane;

    const int lg = lane >> 2;
    const int lt = lane & 3;

    unsigned epoch = 0;

    for (int t = 0; t < T; t++) {
        // ---- prefetch xg + c for cell update (DRAM latency hidden behind mma loop) ----
        float xgv[4], cold;
        {
            const int b  = tid >> 4;
            const int dd = tid & 15;
            if (tid < 256) {
                const size_t xrow = ((size_t)(b * T + t)) * G4;
                xgv[0] = xg[xrow + 0 * DD + d0 + dd];
                xgv[1] = xg[xrow + 1 * DD + d0 + dd];
                xgv[2] = xg[xrow + 2 * DD + d0 + dd];
                xgv[3] = xg[xrow + 3 * DD + d0 + dd];
                cold = c[b * DD + d0 + dd];
            }
        }

        // ---- build h A-fragments in smem (64 ksteps x 32 lanes, hi+lo) ----
#pragma unroll
        for (int i = 0; i < 4; i++) {
            const int e  = tid + i * 512;      // 0..2047
            const int ks = e >> 5;
            const int l  = e & 31;
            const int g  = l >> 2;
            const int tt = l & 3;
            const int k0 = ks * 16;
            float2 p00 = __ldcg((const float2*)&h[g * PP + k0 + 2 * tt]);
            float2 p01 = __ldcg((const float2*)&h[(g + 8) * PP + k0 + 2 * tt]);
            float2 p10 = __ldcg((const float2*)&h[g * PP + k0 + 8 + 2 * tt]);
            float2 p11 = __ldcg((const float2*)&h[(g + 8) * PP + k0 + 8 + 2 * tt]);
            uint4 fh, fl;
            bsplit2(p00.x, p00.y, fh.x, fl.x);
            bsplit2(p01.x, p01.y, fh.y, fl.y);
            bsplit2(p10.x, p10.y, fh.z, fl.z);
            bsplit2(p11.x, p11.y, fh.w, fl.w);
            frag[e * 2 + 0] = fh;
            frag[e * 2 + 1] = fl;
        }
        __syncthreads();

        // ---- phase A mma: gates = h @ Wh slice ----
        float acc[4] = {0.f, 0.f, 0.f, 0.f};
        {
            const uint4* ap = frag + (size_t)(khA * 32) * 64 + lane * 2;
#pragma unroll 4
            for (int ks = 0; ks < 32; ks++) {
                uint4 bfrag = wpA[(size_t)ks * 32];
                uint4 ah = ap[(size_t)ks * 64];
                uint4 al = ap[(size_t)ks * 64 + 1];
                unsigned bh[2] = {bfrag.x, bfrag.y};
                unsigned bl[2] = {bfrag.z, bfrag.w};
                mma_bf16(acc, &ah.x, bh);
                mma_bf16(acc, &ah.x, bl);
                mma_bf16(acc, &al.x, bh);
            }
        }

        // ---- reduce the two k-halves ----
        if (khA == 1) {
#pragma unroll
            for (int r = 0; r < 4; r++) red[(subA * 32 + lane) * 4 + r] = acc[r];
        }
        __syncthreads();
        if (khA == 0) {
#pragma unroll
            for (int r = 0; r < 4; r++) acc[r] += red[(subA * 32 + lane) * 4 + r];
            // scatter into gate buffer gbuf[b][dd][gate]
            const int ddb = halfA * 8 + 2 * lt;
            gbuf[(lg * 16 + ddb) * 4 + gateA]           = acc[0];
            gbuf[(lg * 16 + ddb + 1) * 4 + gateA]       = acc[1];
            gbuf[((lg + 8) * 16 + ddb) * 4 + gateA]     = acc[2];
            gbuf[((lg + 8) * 16 + ddb + 1) * 4 + gateA] = acc[3];
        }
        __syncthreads();

        // ---- cell update ----
        if (tid < 256) {
            const int b  = tid >> 4;
            const int dd = tid & 15;
            const int d  = d0 + dd;
            float4 gv = *(float4*)&gbuf[(b * 16 + dd) * 4];
            float gi = gv.x + xgv[0];
            float gj = gv.y + xgv[1];
            float gf = gv.z + xgv[2];
            float go = gv.w + xgv[3];
            float si = 1.0f / (1.0f + expf(-gi));
            float sf = 1.0f / (1.0f + expf(-(gf + 1.0f)));
            float so = 1.0f / (1.0f + expf(-go));
            float cn = sf * cold + si * tanhf(gj);
            c[b * DD + d] = cn;
            s[b * DD + d] = so * tanhf(cn);
        }

        epoch++;
        grid_barrier(epoch * NBLK);

        // ---- build s A-fragments (128 ksteps x 32 lanes, hi+lo) ----
#pragma unroll
        for (int i = 0; i < 8; i++) {
            const int e  = tid + i * 512;      // 0..4095
            const int ks = e >> 5;
            const int l  = e & 31;
            const int g  = l >> 2;
            const int tt = l & 3;
            const int k0 = ks * 16;
            float2 p00 = __ldcg((const float2*)&s[g * DD + k0 + 2 * tt]);
            float2 p01 = __ldcg((const float2*)&s[(g + 8) * DD + k0 + 2 * tt]);
            float2 p10 = __ldcg((const float2*)&s[g * DD + k0 + 8 + 2 * tt]);
            float2 p11 = __ldcg((const float2*)&s[(g + 8) * DD + k0 + 8 + 2 * tt]);
            uint4 fh, fl;
            bsplit2(p00.x, p00.y, fh.x, fl.x);
            bsplit2(p01.x, p01.y, fh.y, fl.y);
            bsplit2(p10.x, p10.y, fh.z, fl.z);
            bsplit2(p11.x, p11.y, fh.w, fl.w);
            frag[e * 2 + 0] = fh;
            frag[e * 2 + 1] = fl;
        }
        __syncthreads();

        // ---- phase B mma: h = s @ proj slice (warp w covers ksteps [8w, 8w+8)) ----
        float accp[4] = {0.f, 0.f, 0.f, 0.f};
        {
            const uint4* pp = projp + ((size_t)(bid * 128 + warp * 8)) * 32 + lane;
            const uint4* ap = frag + (size_t)(warp * 8) * 64 + lane * 2;
#pragma unroll
            for (int ks = 0; ks < 8; ks++) {
                uint4 bfrag = pp[(size_t)ks * 32];
                uint4 ah = ap[(size_t)ks * 64];
                uint4 al = ap[(size_t)ks * 64 + 1];
                unsigned bh[2] = {bfrag.x, bfrag.y};
                unsigned bl[2] = {bfrag.z, bfrag.w};
                mma_bf16(accp, &ah.x, bh);
                mma_bf16(accp, &ah.x, bl);
                mma_bf16(accp, &al.x, bh);
            }
        }
#pragma unroll
        for (int r = 0; r < 4; r++) red[(warp * 32 + lane) * 4 + r] = accp[r];
        __syncthreads();

        if (tid < 128) {
            const int b = tid >> 3;
            const int p = tid & 7;
            const int rl = (b & 7) * 4 + (p >> 1);
            const int rr = (b < 8) ? (p & 1) : (2 + (p & 1));
            float v = 0.0f;
#pragma unroll
            for (int w = 0; w < 16; w++) v += red[(w * 32 + rl) * 4 + rr];
            h[b * PP + p0 + p] = v;
            hs[((size_t)(b * T + t)) * PP + p0 + p] = v;
        }

        epoch++;
        grid_barrier(epoch * NBLK);
    }
}

// ================= LayerNorm over rows of 1024 =================
__global__ __launch_bounds__(256) void ln_kernel(
    const float* __restrict__ x, const float* __restrict__ gam,
    const float* __restrict__ bet, float* __restrict__ y)
{
    __shared__ float sred[256];
    const size_t r = blockIdx.x;
    const float* xr = x + r * PP;
    const int tid = threadIdx.x;

    float v[4];
#pragma unroll
    for (int i = 0; i < 4; i++) v[i] = xr[tid + i * 256];
    float sm = v[0] + v[1] + v[2] + v[3];
    sred[tid] = sm;
    __syncthreads();
    for (int off = 128; off > 0; off >>= 1) {
        if (tid < off) sred[tid] += sred[tid + off];
        __syncthreads();
    }
    float mean = sred[0] * (1.0f / 1024.0f);
    __syncthreads();

    float q = 0.0f;
#pragma unroll
    for (int i = 0; i < 4; i++) { float d = v[i] - mean; q += d * d; }
    sred[tid] = q;
    __syncthreads();
    for (int off = 128; off > 0; off >>= 1) {
        if (tid < off) sred[tid] += sred[tid + off];
        __syncthreads();
    }
    float inv = rsqrtf(sred[0] * (1.0f / 1024.0f) + 1e-3f);

#pragma unroll
    for (int i = 0; i < 4; i++) {
        int col = tid + i * 256;
        y[r * PP + col] = (v[i] - mean) * inv * gam[col] + bet[col];
    }
}

// ================= conv im2col =================
__global__ __launch_bounds__(256) void build_convA(
    const float* __restrict__ ln, float* __restrict__ Acat)
{
    size_t idx = (size_t)blockIdx.x * 256 + threadIdx.x;
    if (idx >= (size_t)BB * TR * DD) return;
    int m = (int)(idx >> 11);
    int k = (int)(idx & 2047);
    int b = m / TR;
    int t = m - b * TR;
    int w = k >> 10;
    int p = k & 1023;
    Acat[idx] = ln[((size_t)(b * T0 + t + w)) * PP + p];
}

// ================= init / reset / tail =================
__global__ __launch_bounds__(256) void init_state(
    const float* __restrict__ state, float* __restrict__ c, float* __restrict__ h)
{
    int i = blockIdx.x * 256 + threadIdx.x;
    if (i < BB * DD) c[i] = state[i];
    if (i < BB * PP) {
        int b = i >> 10, p = i & 1023;
        h[i] = state[BB * DD + b * DD + p];
    }
}

__global__ void reset_bar() { g_bar = 0u; }

__global__ __launch_bounds__(256) void write_tail(
    const float* __restrict__ c, const float* __restrict__ h, float* __restrict__ out)
{
    const size_t base = (size_t)BB * TR * PP;
    int i = blockIdx.x * 256 + threadIdx.x;
    if (i < BB * DD) out[base + i] = c[i];
    if (i < BB * PP) out[base + BB * DD + i] = h[i];
}

// ================= orchestration =================
extern "C" void kernel_launch(void* const* d_in, const int* in_sizes, int n_in,
                              void* d_out, int out_size)
{
    const float* inputs  = (const float*)d_in[0];
    const float* state   = (const float*)d_in[1];
    const float* kernels = (const float*)d_in[2];
    const float* biases  = (const float*)d_in[3];
    const float* projs   = (const float*)d_in[4];
    const float* gamma   = (const float*)d_in[5];
    const float* beta    = (const float*)d_in[6];
    const float* convw   = (const float*)d_in[7];
    const float* convb   = (const float*)d_in[8];
    float* out = (float*)d_out;

    float *xg, *bufA, *bufB, *convA, *hs, *c, *h, *s;
    uint4 *whp, *projp;
    cudaGetSymbolAddress((void**)&xg,    g_xg);
    cudaGetSymbolAddress((void**)&bufA,  g_bufA);
    cudaGetSymbolAddress((void**)&bufB,  g_bufB);
    cudaGetSymbolAddress((void**)&convA, g_convA);
    cudaGetSymbolAddress((void**)&hs,    g_hs);
    cudaGetSymbolAddress((void**)&whp,   g_whp);
    cudaGetSymbolAddress((void**)&projp, g_projp);
    cudaGetSymbolAddress((void**)&c,     g_c);
    cudaGetSymbolAddress((void**)&h,     g_h);
    cudaGetSymbolAddress((void**)&s,     g_s);

    static int smem_set = 0;
    if (!smem_set) {
        cudaFuncSetAttribute(lstm_persist, cudaFuncAttributeMaxDynamicSharedMemorySize, SMEM_BYTES);
        smem_set = 1;
    }

    init_state<<<128, 256>>>(state, c, h);

    const float* x = inputs;
    int T = T0;
    for (int l = 0; l < NL; l++) {
        const float* Wx = kernels + (size_t)l * 2 * PP * G4;
        const float* Wh = Wx + (size_t)PP * G4;
        const float* bi = biases + (size_t)l * G4;
        const float* pr = projs + (size_t)l * DD * PP;
        const int M = BB * T;

        // pack recurrent weights for this layer (fragment order, bf16 hi/lo)
        pack_frag<<<(1024 * 64) / 8, 256>>>(Wh, whp, G4, 64);     // Wh: 1024x8192, ksteps=64
        pack_frag<<<(128 * 128) / 8, 256>>>(pr, projp, PP, 128);  // proj: 2048x1024, ksteps=128

        dim3 g1(G4 / GBN, (M + GBM - 1) / GBM);
        gemm_tf32<<<g1, 256>>>(x, Wx, bi, xg, M, G4, PP);

        reset_bar<<<1, 1>>>();
        lstm_persist<<<NBLK, 512, SMEM_BYTES>>>(xg, whp, projp, c, h, s, hs, T);

        float* lnout = (l == 0) ? bufA : (l == 1) ? bufB : (l == 2) ? bufA : out;
        ln_kernel<<<BB * T, 256>>>(hs, gamma, beta, lnout);

        if (l == 1) {
            build_convA<<<(BB * TR * DD + 255) / 256, 256>>>(bufB, convA);
            dim3 g2(PP / GBN, (BB * TR + GBM - 1) / GBM);
            gemm_tf32<<<g2, 256>>>(convA, convw, convb, bufA, BB * TR, PP, DD);
            T = TR;
            x = bufA;
        } else {
            x = bufA;
        }
    }

    write_tail<<<128, 256>>>(c, h, out);
}

// round 6
// speedup vs baseline: 2.1237x; 1.6836x over previous
#include <cuda_runtime.h>
#include <cuda_bf16.h>
#include <math.h>

// ---------------- problem constants ----------------
#define BB 16
#define T0 512
#define TR 511
#define PP 1024
#define DD 2048
#define G4 8192   // 4*D
#define NL 4
#define NBLK 128

// ---------------- scratch (device globals; no allocation allowed) ----------------
__device__ __align__(16) float g_xg[(size_t)BB * T0 * G4];      // 256 MB
__device__ __align__(16) float g_bufA[(size_t)BB * T0 * PP];    // 32 MB
__device__ __align__(16) float g_bufB[(size_t)BB * T0 * PP];    // 32 MB
__device__ __align__(16) float g_convA[(size_t)BB * T0 * DD];   // 64 MB
__device__ __align__(16) float g_hs[(size_t)BB * T0 * PP];      // 32 MB
__device__ __align__(16) uint4 g_whp[(size_t)1024 * 64 * 32];   // 32 MB packed Wh fragments
__device__ __align__(16) uint4 g_projp[(size_t)128 * 128 * 32]; // 8 MB packed proj fragments
__device__ __align__(16) uint4 g_hfh[2048];                     // h A-fragments hi (64 ksteps x 32 lanes)
__device__ __align__(16) uint4 g_hfl[2048];                     // h A-fragments lo
__device__ __align__(16) uint4 g_sfh[4096];                     // s A-fragments hi (128 ksteps x 32 lanes)
__device__ __align__(16) uint4 g_sfl[4096];                     // s A-fragments lo
__device__ __align__(16) float g_c[BB * DD];
__device__ __align__(16) float g_h[BB * PP];
__device__ unsigned int g_bar;

// ================= bf16 split helpers =================
__device__ __forceinline__ void bsplit2(float a, float b, unsigned& hi, unsigned& lo) {
    __nv_bfloat162 h2 = __floats2bfloat162_rn(a, b);
    float ra = a - __bfloat162float(h2.x);
    float rb = b - __bfloat162float(h2.y);
    __nv_bfloat162 l2 = __floats2bfloat162_rn(ra, rb);
    hi = *reinterpret_cast<unsigned*>(&h2);
    lo = *reinterpret_cast<unsigned*>(&l2);
}

__device__ __forceinline__ void mma_bf16(float* c, const unsigned* a, const unsigned* b) {
    asm volatile(
        "mma.sync.aligned.m16n8k16.row.col.f32.bf16.bf16.f32 "
        "{%0,%1,%2,%3},{%4,%5,%6,%7},{%8,%9},{%0,%1,%2,%3};"
        : "+f"(c[0]), "+f"(c[1]), "+f"(c[2]), "+f"(c[3])
        : "r"(a[0]), "r"(a[1]), "r"(a[2]), "r"(a[3]), "r"(b[0]), "r"(b[1]));
}

// ================= weight fragment packer =================
// W: K x N row-major. Output: [ntile][kstep][lane] uint4 {b0_hi,b1_hi,b0_lo,b1_lo}.
__global__ __launch_bounds__(256) void pack_frag(
    const float* __restrict__ W, uint4* __restrict__ out, int N, int ksteps)
{
    __shared__ float tile[8][16][8];
    const int wlocal = threadIdx.x >> 5;
    const int lane = threadIdx.x & 31;
    const int wglob = blockIdx.x * 8 + wlocal;
    const int nt = wglob / ksteps;
    const int ks = wglob - nt * ksteps;

    {
        const int r = lane >> 1;
        const int cb = (lane & 1) * 4;
        float4 v = *(const float4*)&W[(size_t)(ks * 16 + r) * N + nt * 8 + cb];
        tile[wlocal][r][cb + 0] = v.x;
        tile[wlocal][r][cb + 1] = v.y;
        tile[wlocal][r][cb + 2] = v.z;
        tile[wlocal][r][cb + 3] = v.w;
    }
    __syncwarp();

    const int g = lane >> 2;
    const int t = lane & 3;
    float v00 = tile[wlocal][2 * t][g];
    float v01 = tile[wlocal][2 * t + 1][g];
    float v10 = tile[wlocal][2 * t + 8][g];
    float v11 = tile[wlocal][2 * t + 9][g];
    uint4 o;
    bsplit2(v00, v01, o.x, o.z);
    bsplit2(v10, v11, o.y, o.w);
    out[((size_t)(nt * ksteps + ks)) * 32 + lane] = o;
}

// ================= split-bf16 GEMM: C[M,N] = A[M,K]@B[K,N] + bias =================
#define GBM 128
#define GBN 128
#define GBK 16
#define ASTR (GBM + 8)
#define BSTR (GBN + 8)

__global__ __launch_bounds__(256) void gemm_bf16(
    const float* __restrict__ A, const float* __restrict__ Bw,
    const float* __restrict__ bias, float* __restrict__ C,
    int M, int N, int K)
{
    __shared__ float As[GBK][ASTR];
    __shared__ float Bs[GBK][BSTR];

    const int bm = blockIdx.y * GBM;
    const int bn = blockIdx.x * GBN;
    const int tid = threadIdx.x;
    const int lane = tid & 31;
    const int wid = tid >> 5;
    const int wm = (wid >> 2) * 64;
    const int wn = (wid & 3) * 32;
    const int lg = lane >> 2;
    const int lk = lane & 3;

    float acc[4][4][4];
#pragma unroll
    for (int mt = 0; mt < 4; mt++)
#pragma unroll
        for (int nt = 0; nt < 4; nt++)
#pragma unroll
            for (int r = 0; r < 4; r++) acc[mt][nt][r] = 0.0f;

    for (int k0 = 0; k0 < K; k0 += GBK) {
#pragma unroll
        for (int it = 0; it < 2; it++) {
            int f = tid + it * 256;
            int r = f >> 2;
            int kq = (f & 3) * 4;
            float4 v = make_float4(0.f, 0.f, 0.f, 0.f);
            if (bm + r < M) v = *(const float4*)&A[(size_t)(bm + r) * K + k0 + kq];
            As[kq + 0][r] = v.x;
            As[kq + 1][r] = v.y;
            As[kq + 2][r] = v.z;
            As[kq + 3][r] = v.w;
        }
#pragma unroll
        for (int it = 0; it < 2; it++) {
            int f = tid + it * 256;
            int r = f >> 5;
            int nq = (f & 31) * 4;
            float4 v = *(const float4*)&Bw[(size_t)(k0 + r) * N + bn + nq];
            *(float4*)&Bs[r][nq] = v;
        }
        __syncthreads();

        // one k16 chunk per tile: bf16-split fragments, 3-mma scheme
        {
            unsigned ah[4][4], al[4][4], bh[4][2], bl[4][2];
#pragma unroll
            for (int mt = 0; mt < 4; mt++) {
                int row = wm + mt * 16 + lg;
                bsplit2(As[2 * lk][row],     As[2 * lk + 1][row],     ah[mt][0], al[mt][0]);
                bsplit2(As[2 * lk][row + 8], As[2 * lk + 1][row + 8], ah[mt][1], al[mt][1]);
                bsplit2(As[8 + 2 * lk][row],     As[9 + 2 * lk][row],     ah[mt][2], al[mt][2]);
                bsplit2(As[8 + 2 * lk][row + 8], As[9 + 2 * lk][row + 8], ah[mt][3], al[mt][3]);
            }
#pragma unroll
            for (int nt = 0; nt < 4; nt++) {
                int col = wn + nt * 8 + lg;
                bsplit2(Bs[2 * lk][col], Bs[2 * lk + 1][col], bh[nt][0], bl[nt][0]);
                bsplit2(Bs[8 + 2 * lk][col], Bs[9 + 2 * lk][col], bh[nt][1], bl[nt][1]);
            }
#pragma unroll
            for (int mt = 0; mt < 4; mt++)
#pragma unroll
                for (int nt = 0; nt < 4; nt++) {
                    mma_bf16(acc[mt][nt], ah[mt], bh[nt]);
                    mma_bf16(acc[mt][nt], ah[mt], bl[nt]);
                    mma_bf16(acc[mt][nt], al[mt], bh[nt]);
                }
        }
        __syncthreads();
    }

#pragma unroll
    for (int mt = 0; mt < 4; mt++) {
#pragma unroll
        for (int nt = 0; nt < 4; nt++) {
            int row0 = bm + wm + mt * 16 + lg;
            int col0 = bn + wn + nt * 8 + lk * 2;
            float b0 = bias[col0], b1 = bias[col0 + 1];
            if (row0 < M) {
                float2 v = make_float2(acc[mt][nt][0] + b0, acc[mt][nt][1] + b1);
                *(float2*)&C[(size_t)row0 * N + col0] = v;
            }
            if (row0 + 8 < M) {
                float2 v = make_float2(acc[mt][nt][2] + b0, acc[mt][nt][3] + b1);
                *(float2*)&C[(size_t)(row0 + 8) * N + col0] = v;
            }
        }
    }
}

// ================= persistent LSTM layer kernel (tensor-core, frag-native state) =================
__device__ __forceinline__ void grid_barrier(unsigned target) {
    __syncthreads();
    __threadfence();
    if (threadIdx.x == 0) {
        atomicAdd(&g_bar, 1u);
        while (*(volatile unsigned int*)&g_bar < target) {
            __nanosleep(20);
        }
    }
    __syncthreads();
}

// smem: h-frag hi 32KB + h-frag lo 32KB + red/gbuf 8KB = 72KB
#define SMEM_BYTES (72 * 1024)

__global__ __launch_bounds__(512, 1) void lstm_persist(
    const float* __restrict__ xg,       // (B*T, 8192)
    const uint4* __restrict__ whp,      // packed Wh fragments [1024][64][32]
    const uint4* __restrict__ projp,    // packed proj fragments [128][128][32]
    float* __restrict__ c,              // (16, 2048)
    float* __restrict__ h,              // (16, 1024) scalar (for tail)
    float* __restrict__ hs,             // (B*T, 1024)
    int T)
{
    extern __shared__ __align__(16) char dynsmem[];
    uint4* sh_hi = (uint4*)dynsmem;                 // 2048 uint4
    uint4* sh_lo = sh_hi + 2048;                    // 2048 uint4
    float* red   = (float*)(dynsmem + 64 * 1024);   // 2048 floats (red[0..1024) + gbuf)
    float* gbuf  = red + 1024;

    unsigned* sfh32 = (unsigned*)g_sfh;
    unsigned* sfl32 = (unsigned*)g_sfl;
    unsigned* hfh32 = (unsigned*)g_hfh;
    unsigned* hfl32 = (unsigned*)g_hfl;

    const int tid  = threadIdx.x;
    const int lane = tid & 31;
    const int warp = tid >> 5;        // 0..15
    const int bid  = blockIdx.x;
    const int d0   = bid * 16;
    const int p0   = bid * 8;

    // phase A warp mapping
    const int subA = warp & 7;
    const int khA  = warp >> 3;       // k-half of 1024
    const int gateA = subA >> 1;
    const int halfA = subA & 1;
    const int ntA  = gateA * 256 + bid * 2 + halfA;
    const uint4* wpA = whp + ((size_t)(ntA * 64 + khA * 32)) * 32 + lane;

    const int lg = lane >> 2;
    const int lt = lane & 3;

    // cell-update mapping (tid < 128): b row, jj = local d-pair
    const int cb = tid >> 3;
    const int cj = tid & 7;
    // s-frag word index for this thread's pair: ks=bid, khalf=(cj>>2)&1, t=cj&3
    const int s_idx = (((bid * 32) + (cb & 7) * 4 + (cj & 3)) << 2) + ((cb >> 3) + 2 * ((cj >> 2) & 1));
    // h-frag word index (phase B, even-p threads): p=tid&7, pp=p>>1
    const int hb = tid >> 3;
    const int hp = tid & 7;
    const int h_idx = ((((bid >> 1) * 32) + (hb & 7) * 4 + (hp >> 1)) << 2) + ((hb >> 3) + 2 * (bid & 1));

    unsigned epoch = 0;

    for (int t = 0; t < T; t++) {
        // ---- prefetch xg (4 gates x d-pair) + old c ----
        float2 xgv[4], cold;
        if (tid < 128) {
            const size_t xrow = ((size_t)(cb * T + t)) * G4;
            const int dloc = d0 + 2 * cj;
#pragma unroll
            for (int g = 0; g < 4; g++)
                xgv[g] = *(const float2*)&xg[xrow + g * DD + dloc];
            cold = *(const float2*)&c[cb * DD + dloc];
        }

        // ---- stage h A-fragments global -> smem (written frag-native by phase B / init) ----
#pragma unroll
        for (int i = 0; i < 4; i++) {
            const int idx = tid + i * 512;
            sh_hi[idx] = __ldcg(&g_hfh[idx]);
            sh_lo[idx] = __ldcg(&g_hfl[idx]);
        }
        __syncthreads();

        // ---- phase A mma: gates = h @ Wh slice ----
        float acc[4] = {0.f, 0.f, 0.f, 0.f};
        {
            const uint4* aph = sh_hi + (khA * 32) * 32 + lane;
            const uint4* apl = sh_lo + (khA * 32) * 32 + lane;
#pragma unroll 4
            for (int ks = 0; ks < 32; ks++) {
                uint4 bfrag = wpA[(size_t)ks * 32];
                uint4 ah = aph[ks * 32];
                uint4 al = apl[ks * 32];
                unsigned bh[2] = {bfrag.x, bfrag.y};
                unsigned bl[2] = {bfrag.z, bfrag.w};
                mma_bf16(acc, &ah.x, bh);
                mma_bf16(acc, &ah.x, bl);
                mma_bf16(acc, &al.x, bh);
            }
        }

        // ---- reduce the two k-halves ----
        if (khA == 1) {
#pragma unroll
            for (int r = 0; r < 4; r++) red[(subA * 32 + lane) * 4 + r] = acc[r];
        }
        __syncthreads();
        if (khA == 0) {
#pragma unroll
            for (int r = 0; r < 4; r++) acc[r] += red[(subA * 32 + lane) * 4 + r];
            const int ddb = halfA * 8 + 2 * lt;
            gbuf[(lg * 16 + ddb) * 4 + gateA]           = acc[0];
            gbuf[(lg * 16 + ddb + 1) * 4 + gateA]       = acc[1];
            gbuf[((lg + 8) * 16 + ddb) * 4 + gateA]     = acc[2];
            gbuf[((lg + 8) * 16 + ddb + 1) * 4 + gateA] = acc[3];
        }
        __syncthreads();

        // ---- cell update: writes c (scalar) and s (fragment-native) ----
        if (tid < 128) {
            float4 gv0 = *(float4*)&gbuf[(cb * 16 + 2 * cj) * 4];
            float4 gv1 = *(float4*)&gbuf[(cb * 16 + 2 * cj + 1) * 4];
            // cell 0
            float si0 = 1.0f / (1.0f + expf(-(gv0.x + xgv[0].x)));
            float sj0 = tanhf(gv0.y + xgv[1].x);
            float sf0 = 1.0f / (1.0f + expf(-(gv0.z + xgv[2].x + 1.0f)));
            float so0 = 1.0f / (1.0f + expf(-(gv0.w + xgv[3].x)));
            float cn0 = sf0 * cold.x + si0 * sj0;
            float s0 = so0 * tanhf(cn0);
            // cell 1
            float si1 = 1.0f / (1.0f + expf(-(gv1.x + xgv[0].y)));
            float sj1 = tanhf(gv1.y + xgv[1].y);
            float sf1 = 1.0f / (1.0f + expf(-(gv1.z + xgv[2].y + 1.0f)));
            float so1 = 1.0f / (1.0f + expf(-(gv1.w + xgv[3].y)));
            float cn1 = sf1 * cold.y + si1 * sj1;
            float s1 = so1 * tanhf(cn1);

            *(float2*)&c[cb * DD + d0 + 2 * cj] = make_float2(cn0, cn1);

            unsigned hiw, low;
            bsplit2(s0, s1, hiw, low);
            sfh32[s_idx] = hiw;
            sfl32[s_idx] = low;
        }

        epoch++;
        grid_barrier(epoch * NBLK);

        // ---- phase B mma: h = s @ proj (warp w covers ksteps [8w, 8w+8), frags from L2) ----
        float accp[4] = {0.f, 0.f, 0.f, 0.f};
        {
            const uint4* pp = projp + ((size_t)(bid * 128 + warp * 8)) * 32 + lane;
            const uint4* aph = g_sfh + (warp * 8) * 32 + lane;
            const uint4* apl = g_sfl + (warp * 8) * 32 + lane;
#pragma unroll
            for (int ks = 0; ks < 8; ks++) {
                uint4 bfrag = pp[(size_t)ks * 32];
                uint4 ah = __ldcg(&aph[ks * 32]);
                uint4 al = __ldcg(&apl[ks * 32]);
                unsigned bh[2] = {bfrag.x, bfrag.y};
                unsigned bl[2] = {bfrag.z, bfrag.w};
                mma_bf16(accp, &ah.x, bh);
                mma_bf16(accp, &ah.x, bl);
                mma_bf16(accp, &al.x, bh);
            }
        }
#pragma unroll
        for (int r = 0; r < 4; r++) red[(warp * 32 + lane) * 4 + r] = accp[r];
        __syncthreads();

        if (tid < 128) {
            const int b = hb;
            const int p = hp;
            const int rl = (b & 7) * 4 + (p >> 1);
            const int rr = (b < 8) ? (p & 1) : (2 + (p & 1));
            float v = 0.0f;
#pragma unroll
            for (int w = 0; w < 16; w++) v += red[(w * 32 + rl) * 4 + rr];
            h[b * PP + p0 + p] = v;
            hs[((size_t)(b * T + t)) * PP + p0 + p] = v;
            // fragment-native h for next step's phase A
            float vp = __shfl_xor_sync(0xffffffffu, v, 1);
            if ((tid & 1) == 0) {
                unsigned hiw, low;
                bsplit2(v, vp, hiw, low);
                hfh32[h_idx] = hiw;
                hfl32[h_idx] = low;
            }
        }

        epoch++;
        grid_barrier(epoch * NBLK);
    }
}

// ================= pack initial h into fragment form =================
__global__ __launch_bounds__(256) void pack_h_init(const float* __restrict__ h)
{
    unsigned* hfh32 = (unsigned*)g_hfh;
    unsigned* hfl32 = (unsigned*)g_hfl;
    int idx = blockIdx.x * 256 + threadIdx.x;   // 8192 words: b*512 + j
    if (idx >= BB * 512) return;
    int b = idx >> 9;
    int j = idx & 511;
    float v0 = h[b * PP + 2 * j];
    float v1 = h[b * PP + 2 * j + 1];
    int ks = j >> 3;
    int khalf = (j >> 2) & 1;
    int tq = j & 3;
    int lane = (b & 7) * 4 + tq;
    int comp = (b >> 3) + 2 * khalf;
    unsigned hiw, low;
    bsplit2(v0, v1, hiw, low);
    hfh32[((ks * 32 + lane) << 2) + comp] = hiw;
    hfl32[((ks * 32 + lane) << 2) + comp] = low;
}

// ================= LayerNorm over rows of 1024 =================
__global__ __launch_bounds__(256) void ln_kernel(
    const float* __restrict__ x, const float* __restrict__ gam,
    const float* __restrict__ bet, float* __restrict__ y)
{
    __shared__ float sred[256];
    const size_t r = blockIdx.x;
    const float* xr = x + r * PP;
    const int tid = threadIdx.x;

    float v[4];
#pragma unroll
    for (int i = 0; i < 4; i++) v[i] = xr[tid + i * 256];
    float sm = v[0] + v[1] + v[2] + v[3];
    sred[tid] = sm;
    __syncthreads();
    for (int off = 128; off > 0; off >>= 1) {
        if (tid < off) sred[tid] += sred[tid + off];
        __syncthreads();
    }
    float mean = sred[0] * (1.0f / 1024.0f);
    __syncthreads();

    float q = 0.0f;
#pragma unroll
    for (int i = 0; i < 4; i++) { float d = v[i] - mean; q += d * d; }
    sred[tid] = q;
    __syncthreads();
    for (int off = 128; off > 0; off >>= 1) {
        if (tid < off) sred[tid] += sred[tid + off];
        __syncthreads();
    }
    float inv = rsqrtf(sred[0] * (1.0f / 1024.0f) + 1e-3f);

#pragma unroll
    for (int i = 0; i < 4; i++) {
        int col = tid + i * 256;
        y[r * PP + col] = (v[i] - mean) * inv * gam[col] + bet[col];
    }
}

// ================= conv im2col =================
__global__ __launch_bounds__(256) void build_convA(
    const float* __restrict__ ln, float* __restrict__ Acat)
{
    size_t idx = (size_t)blockIdx.x * 256 + threadIdx.x;
    if (idx >= (size_t)BB * TR * DD) return;
    int m = (int)(idx >> 11);
    int k = (int)(idx & 2047);
    int b = m / TR;
    int t = m - b * TR;
    int w = k >> 10;
    int p = k & 1023;
    Acat[idx] = ln[((size_t)(b * T0 + t + w)) * PP + p];
}

// ================= init / reset / tail =================
__global__ __launch_bounds__(256) void init_state(
    const float* __restrict__ state, float* __restrict__ c, float* __restrict__ h)
{
    int i = blockIdx.x * 256 + threadIdx.x;
    if (i < BB * DD) c[i] = state[i];
    if (i < BB * PP) {
        int b = i >> 10, p = i & 1023;
        h[i] = state[BB * DD + b * DD + p];
    }
}

__global__ void reset_bar() { g_bar = 0u; }

__global__ __launch_bounds__(256) void write_tail(
    const float* __restrict__ c, const float* __restrict__ h, float* __restrict__ out)
{
    const size_t base = (size_t)BB * TR * PP;
    int i = blockIdx.x * 256 + threadIdx.x;
    if (i < BB * DD) out[base + i] = c[i];
    if (i < BB * PP) out[base + BB * DD + i] = h[i];
}

// ================= orchestration =================
extern "C" void kernel_launch(void* const* d_in, const int* in_sizes, int n_in,
                              void* d_out, int out_size)
{
    const float* inputs  = (const float*)d_in[0];
    const float* state   = (const float*)d_in[1];
    const float* kernels = (const float*)d_in[2];
    const float* biases  = (const float*)d_in[3];
    const float* projs   = (const float*)d_in[4];
    const float* gamma   = (const float*)d_in[5];
    const float* beta    = (const float*)d_in[6];
    const float* convw   = (const float*)d_in[7];
    const float* convb   = (const float*)d_in[8];
    float* out = (float*)d_out;

    float *xg, *bufA, *bufB, *convA, *hs, *c, *h;
    uint4 *whp, *projp;
    cudaGetSymbolAddress((void**)&xg,    g_xg);
    cudaGetSymbolAddress((void**)&bufA,  g_bufA);
    cudaGetSymbolAddress((void**)&bufB,  g_bufB);
    cudaGetSymbolAddress((void**)&convA, g_convA);
    cudaGetSymbolAddress((void**)&hs,    g_hs);
    cudaGetSymbolAddress((void**)&whp,   g_whp);
    cudaGetSymbolAddress((void**)&projp, g_projp);
    cudaGetSymbolAddress((void**)&c,     g_c);
    cudaGetSymbolAddress((void**)&h,     g_h);

    static int smem_set = 0;
    if (!smem_set) {
        cudaFuncSetAttribute(lstm_persist, cudaFuncAttributeMaxDynamicSharedMemorySize, SMEM_BYTES);
        smem_set = 1;
    }

    init_state<<<128, 256>>>(state, c, h);
    pack_h_init<<<32, 256>>>(h);

    const float* x = inputs;
    int T = T0;
    for (int l = 0; l < NL; l++) {
        const float* Wx = kernels + (size_t)l * 2 * PP * G4;
        const float* Wh = Wx + (size_t)PP * G4;
        const float* bi = biases + (size_t)l * G4;
        const float* pr = projs + (size_t)l * DD * PP;
        const int M = BB * T;

        pack_frag<<<(1024 * 64) / 8, 256>>>(Wh, whp, G4, 64);
        pack_frag<<<(128 * 128) / 8, 256>>>(pr, projp, PP, 128);

        dim3 g1(G4 / GBN, (M + GBM - 1) / GBM);
        gemm_bf16<<<g1, 256>>>(x, Wx, bi, xg, M, G4, PP);

        reset_bar<<<1, 1>>>();
        lstm_persist<<<NBLK, 512, SMEM_BYTES>>>(xg, whp, projp, c, h, hs, T);

        float* lnout = (l == 0) ? bufA : (l == 1) ? bufB : (l == 2) ? bufA : out;
        ln_kernel<<<BB * T, 256>>>(hs, gamma, beta, lnout);

        if (l == 1) {
            build_convA<<<(BB * TR * DD + 255) / 256, 256>>>(bufB, convA);
            dim3 g2(PP / GBN, (BB * TR + GBM - 1) / GBM);
            gemm_bf16<<<g2, 256>>>(convA, convw, convb, bufA, BB * TR, PP, DD);
            T = TR;
            x = bufA;
        } else {
            x = bufA;
        }
    }

    write_tail<<<128, 256>>>(c, h, out);
}